// round 8
// baseline (speedup 1.0000x reference)
#include <cuda_runtime.h>

#define BB 32
#define NN 2048
#define EPSF 5e-4f
#define HH 5.0f
#define MC 28            /* Chebyshev-Gauss nodes; interpolant degree 27 */

__device__ float g_Fp[BB*8*32];   // node partials [row][blk][lane]
__device__ float g_inv[BB];       // 1/max(maxDCG,EPS)
__device__ float g_rowSum[BB];
__device__ int   g_rowCtr[BB];    // zero-init; self-resetting
__device__ int   g_ctr;           // zero-init; self-resetting

// Single kernel, grid (9, BB) x 512.
//  blk<8 : node partial sums over 128 score-pairs (8 paired sigmoids/thread)
//          sig(a)+sig(b) at node W: (2ab+pW)/(W^2+pW+ab), p=a+b, W=e^{x_k}.
//  blk==8: label histogram -> rank-based maxDCG -> g_inv (off critical path).
//  Last arriver per row: fold partials, warp-parallel DCT-II, Clenshaw at
//  4 pts/thread, row sum. Last row finisher writes the mean.
__global__ __launch_bounds__(512, 2)
void fused(const float* __restrict__ yp, const float* __restrict__ yt,
           float* __restrict__ out) {
    int blk = blockIdx.x, b = blockIdx.y;
    int t = threadIdx.x, w = t >> 5, lane = t & 31;
    __shared__ float2 sP[128];
    __shared__ float sF[576];         // 16*33 pair partials; [512..539]=Fn
    __shared__ float sCoef[MC];
    __shared__ float sRed[16];
    __shared__ unsigned long long sH[16];
    __shared__ int sOff[4];
    __shared__ int sFlag;

    if (blk < 8) {
        // ---- pair phase: this block owns scores [blk*256, blk*256+256) ----
        if (t < 128) {
            float2 sc = ((const float2*)(yp + b*NN + blk*256))[t];
            float ea = __expf(sc.x), eb = __expf(sc.y);
            sP[t] = make_float2(ea + eb, 2.f*ea*eb);
        }
        // lane = node k: x_k = HH*cos(pi(2k+1)/(2*MC)); lanes >= MC produce junk
        // that is never read by the fold below.
        float W  = __expf(HH * cospif((float)(2*lane + 1) * (1.0f/(2*MC))));
        float W2 = W * W;
        __syncthreads();
        const float4* P4 = (const float4*)sP;       // (p0,r2_0,p1,r2_1)
        float acc = 0.f;
        #pragma unroll
        for (int i = 0; i < 4; i++) {
            float4 q = P4[w*4 + i];
            acc = fmaf(fmaf(q.x, W, q.y),
                       __frcp_rn(fmaf(q.x, W, fmaf(0.5f, q.y, W2))), acc);
            acc = fmaf(fmaf(q.z, W, q.w),
                       __frcp_rn(fmaf(q.z, W, fmaf(0.5f, q.w, W2))), acc);
        }
        sF[w*33 + lane] = acc;
        __syncthreads();
        if (w == 0) {
            float F = 0.f;
            #pragma unroll
            for (int i = 0; i < 16; i++) F += sF[i*33 + lane];
            g_Fp[(b*8 + blk)*32 + lane] = F;
        }
    } else {
        // ---- histogram block: rank-based maxDCG -> g_inv[b] ----
        float4 lb = ((const float4*)(yt + b*NN))[t];
        int v0 = (int)lb.x, v1 = (int)lb.y, v2 = (int)lb.z, v3 = (int)lb.w;
        unsigned long long pk = (1ULL << (12*v0)) + (1ULL << (12*v1))
                              + (1ULL << (12*v2)) + (1ULL << (12*v3));
        #pragma unroll
        for (int o = 16; o; o >>= 1) pk += __shfl_xor_sync(0xffffffffu, pk, o);
        if (lane == 0) sH[w] = pk;
        __syncthreads();
        if (w == 0) {
            unsigned long long hh = (lane < 16) ? sH[lane] : 0ULL;
            #pragma unroll
            for (int o = 8; o; o >>= 1) hh += __shfl_xor_sync(0xffffffffu, hh, o);
            if (lane == 0) {
                int c4 = (int)((hh >> 48) & 0xFFF);
                int c3 = (int)((hh >> 36) & 0xFFF);
                int c2 = (int)((hh >> 24) & 0xFFF);
                int c1 = (int)((hh >> 12) & 0xFFF);
                sOff[0] = c4;  sOff[1] = c4 + c3;
                sOff[2] = c4 + c3 + c2;  sOff[3] = c4 + c3 + c2 + c1;
            }
        }
        __syncthreads();
        int B4 = sOff[0], B3 = sOff[1], B2 = sOff[2], B1 = sOff[3];
        float mdcg = 0.f;
        #pragma unroll
        for (int i = 0; i < 4; i++) {
            int n = t + i*512;                   // rank r = n (0-based)
            int vr = 4 - (n >= B4) - (n >= B3) - (n >= B2) - (n >= B1);
            mdcg += __fdividef((float)((1 << vr) - 1), __log2f((float)(n + 2)));
        }
        #pragma unroll
        for (int o = 16; o; o >>= 1) mdcg += __shfl_xor_sync(0xffffffffu, mdcg, o);
        if (lane == 0) sRed[w] = mdcg;
        __syncthreads();
        if (w == 0) {
            float x = (lane < 16) ? sRed[lane] : 0.f;
            #pragma unroll
            for (int o = 8; o; o >>= 1) x += __shfl_xor_sync(0xffffffffu, x, o);
            if (lane == 0) g_inv[b] = 1.0f / fmaxf(x, EPSF);
        }
    }

    // ---- row arrival: last of 9 blocks becomes the eval finisher ----
    if (t == 0) {
        __threadfence();
        int d = atomicAdd(&g_rowCtr[b], 1);
        sFlag = (d == 8);
        if (sFlag) g_rowCtr[b] = 0;              // self-reset for graph replay
    }
    __syncthreads();
    if (!sFlag) return;
    __threadfence();

    // ---- fold node partials ----
    if (t < 256) sF[t] = g_Fp[b*256 + t];        // [blk*32 + lane]
    __syncthreads();
    if (t < 32) {
        float F = 0.f;
        #pragma unroll
        for (int i = 0; i < 8; i++) F += sF[i*32 + t];
        sF[512 + t] = F;
    }
    __syncthreads();

    // ---- warp-parallel DCT-II: c_m = (2/MC) sum_k F_k cos(pi m(2k+1)/(2MC)) ----
    float Fk = (lane < MC) ? sF[512 + lane] : 0.f;
    if (w < 14) {
        #pragma unroll
        for (int j = 0; j < 2; j++) {
            int m = w + 14*j;
            float term = Fk * cospif((float)(m*(2*lane + 1)) * (1.0f/(2*MC)));
            #pragma unroll
            for (int o = 16; o; o >>= 1) term += __shfl_xor_sync(0xffffffffu, term, o);
            if (lane == 0) {
                float cc = term * (2.0f/MC);
                if (m == 0) cc *= 0.5f;
                sCoef[m] = cc;
            }
        }
    }
    __syncthreads();

    // ---- Clenshaw eval at 4 pts/thread + row NDCG sum ----
    float4 s4 = ((const float4*)(yp + b*NN))[t];
    float4 l4 = ((const float4*)(yt + b*NN))[t];
    float inv = g_inv[b];
    float ss[4] = {s4.x, s4.y, s4.z, s4.w};
    int   vv[4] = {(int)l4.x, (int)l4.y, (int)l4.z, (int)l4.w};
    float numer = 0.f;
    #pragma unroll
    for (int i = 0; i < 4; i++) {
        float u = fminf(fmaxf(ss[i] * (1.0f/HH), -1.f), 1.f);
        float tu = u + u, y1 = 0.f, y2 = 0.f;
        #pragma unroll
        for (int m = MC - 1; m >= 1; m--) {
            float tmp = fmaf(tu, y1, sCoef[m]) - y2;
            y2 = y1; y1 = tmp;
        }
        float F = fmaf(u, y1, sCoef[0]) - y2;            // interpolated F(s)
        float gain = (float)((1 << vv[i]) - 1);
        numer += __fdividef(gain, __log2f(1.5f + F));    // pos = 0.5 + F
    }
    #pragma unroll
    for (int o = 16; o; o >>= 1) numer += __shfl_xor_sync(0xffffffffu, numer, o);
    if (lane == 0) sRed[w] = numer;
    __syncthreads();
    if (w == 0) {
        float x = (lane < 16) ? sRed[lane] : 0.f;
        #pragma unroll
        for (int o = 8; o; o >>= 1) x += __shfl_xor_sync(0xffffffffu, x, o);
        if (lane == 0) {
            g_rowSum[b] = x * inv;
            __threadfence();
            int d = atomicAdd(&g_ctr, 1);
            if (d == BB - 1) {                   // last row finisher -> mean
                g_ctr = 0;                       // self-reset
                __threadfence();
                float sAll = 0.f;
                #pragma unroll
                for (int i = 0; i < BB; i++) sAll += g_rowSum[i];
                out[0] = sAll * (1.0f/BB);
            }
        }
    }
}

extern "C" void kernel_launch(void* const* d_in, const int* in_sizes, int n_in,
                              void* d_out, int out_size) {
    const float* yp = (const float*)d_in[0];
    const float* yt = (const float*)d_in[1];
    float* out = (float*)d_out;
    (void)in_sizes; (void)n_in; (void)out_size;

    dim3 g(9, BB);
    fused<<<g, 512>>>(yp, yt, out);
}

// round 11
// speedup vs baseline: 1.2143x; 1.2143x over previous
#include <cuda_runtime.h>

#define BB 32
#define NN 2048
#define EPSF 5e-4f
#define HH 5.0f
#define MC 28            /* Chebyshev-Gauss nodes; degree 27 */
#define PBLK 4           /* pair blocks per row */

__device__ float g_Fp[BB*PBLK*32];   // node partials [row][blk][lane]
__device__ float g_rowSum[BB];
__device__ int   g_rowCtr[BB];       // zero-init; finisher resets
__device__ int   g_ctr;              // zero-init; self-resetting

// Grid (PBLK+1, BB) x 512.
//  blk<PBLK : node partial sums over 512 scores (16 paired sigmoids/warp):
//             sig(a)+sig(b) at node W: (2ab+pW)/(ab+pW+W^2), p=a+b, W=e^{x_k}.
//             Write partials, fence, arrive on row counter.
//  blk==PBLK: designated finisher. Overlapped with pair phase: preload eval
//             scores/labels to registers, histogram -> rank-based maxDCG -> inv.
//             Then spin on row counter (all blocks co-resident by occupancy),
//             fold partials, warp-parallel DCT-II, Clenshaw 4 pts/thread,
//             row sum; last row finisher computes the mean (warp-parallel).
__global__ __launch_bounds__(512, 2)
void fused(const float* __restrict__ yp, const float* __restrict__ yt,
           float* __restrict__ out) {
    int blk = blockIdx.x, b = blockIdx.y;
    int t = threadIdx.x, w = t >> 5, lane = t & 31;

    if (blk < PBLK) {
        // ------------- pair phase: scores [blk*512, blk*512+512) -------------
        __shared__ float2 sP[256];
        __shared__ float sF[16*33];
        if (t < 256) {
            float2 sc = ((const float2*)(yp + b*NN + blk*512))[t];
            float ea = __expf(sc.x), eb = __expf(sc.y);
            sP[t] = make_float2(ea + eb, 2.f*ea*eb);
        }
        // lane = node k: x_k = HH*cos(pi(2k+1)/(2*MC)); lanes >= MC junk, unread.
        float W  = __expf(HH * cospif((float)(2*lane + 1) * (1.0f/(2*MC))));
        float W2 = W * W;
        __syncthreads();
        const float4* P4 = (const float4*)(sP + w*16);   // (p0,r0,p1,r1) x8
        float acc = 0.f;
        #pragma unroll
        for (int i = 0; i < 8; i++) {
            float4 q = P4[i];
            acc = fmaf(fmaf(q.x, W, q.y),
                       __frcp_rn(fmaf(q.x, W, fmaf(0.5f, q.y, W2))), acc);
            acc = fmaf(fmaf(q.z, W, q.w),
                       __frcp_rn(fmaf(q.z, W, fmaf(0.5f, q.w, W2))), acc);
        }
        sF[w*33 + lane] = acc;
        __syncthreads();
        if (w == 0) {
            float F = 0.f;
            #pragma unroll
            for (int i = 0; i < 16; i++) F += sF[i*33 + lane];
            g_Fp[(b*PBLK + blk)*32 + lane] = F;
        }
        __syncthreads();
        if (t == 0) {
            __threadfence();
            atomicAdd(&g_rowCtr[b], 1);
        }
        return;
    }

    // ---------------------- designated finisher block ----------------------
    __shared__ float sFp[PBLK*32];
    __shared__ float sFn[32];
    __shared__ float sCoef[MC];
    __shared__ float sRed[16];
    __shared__ unsigned long long sH[16];
    __shared__ int sOff[4];

    // preload eval data (DRAM latency overlapped with pair blocks' work)
    float4 s4 = ((const float4*)(yp + b*NN))[t];
    float4 l4 = ((const float4*)(yt + b*NN))[t];
    int vv[4] = {(int)l4.x, (int)l4.y, (int)l4.z, (int)l4.w};

    // packed label histogram
    unsigned long long pk = (1ULL << (12*vv[0])) + (1ULL << (12*vv[1]))
                          + (1ULL << (12*vv[2])) + (1ULL << (12*vv[3]));
    #pragma unroll
    for (int o = 16; o; o >>= 1) pk += __shfl_xor_sync(0xffffffffu, pk, o);
    if (lane == 0) sH[w] = pk;
    __syncthreads();
    if (w == 0) {
        unsigned long long hh = (lane < 16) ? sH[lane] : 0ULL;
        #pragma unroll
        for (int o = 8; o; o >>= 1) hh += __shfl_xor_sync(0xffffffffu, hh, o);
        if (lane == 0) {
            int c4 = (int)((hh >> 48) & 0xFFF);
            int c3 = (int)((hh >> 36) & 0xFFF);
            int c2 = (int)((hh >> 24) & 0xFFF);
            int c1 = (int)((hh >> 12) & 0xFFF);
            sOff[0] = c4;  sOff[1] = c4 + c3;
            sOff[2] = c4 + c3 + c2;  sOff[3] = c4 + c3 + c2 + c1;
        }
    }
    __syncthreads();

    // rank-based maxDCG -> inv (kept in smem via sRed reuse)
    int B4 = sOff[0], B3 = sOff[1], B2 = sOff[2], B1 = sOff[3];
    float mdcg = 0.f;
    #pragma unroll
    for (int i = 0; i < 4; i++) {
        int n = t + i*512;                        // rank r = n (0-based)
        int vr = 4 - (n >= B4) - (n >= B3) - (n >= B2) - (n >= B1);
        mdcg += __fdividef((float)((1 << vr) - 1), __log2f((float)(n + 2)));
    }
    #pragma unroll
    for (int o = 16; o; o >>= 1) mdcg += __shfl_xor_sync(0xffffffffu, mdcg, o);
    if (lane == 0) sRed[w] = mdcg;
    __syncthreads();
    float inv;
    if (t == 0) {
        float x = 0.f;
        #pragma unroll
        for (int i = 0; i < 16; i++) x += sRed[i];
        sFn[0] = 1.0f / fmaxf(x, EPSF);           // stash inv
        // spin for the row's pair blocks (all co-resident; bounded work)
        while (*(volatile int*)&g_rowCtr[b] != PBLK) __nanosleep(64);
        g_rowCtr[b] = 0;                          // reset for next replay
    }
    __syncthreads();
    inv = sFn[0];
    __threadfence();                              // acquire partials

    // fold node partials
    if (t < PBLK*32) sFp[t] = g_Fp[b*PBLK*32 + t];
    __syncthreads();
    if (t < 32) {
        float F = 0.f;
        #pragma unroll
        for (int i = 0; i < PBLK; i++) F += sFp[i*32 + t];
        sFn[t] = F;                               // (sFn[0] no longer needed)
    }
    __syncthreads();

    // warp-parallel DCT-II: c_m = (2/MC) sum_k F_k cos(pi m(2k+1)/(2MC))
    float Fk = (lane < MC) ? sFn[lane] : 0.f;
    if (w < 14) {
        #pragma unroll
        for (int j = 0; j < 2; j++) {
            int m = w + 14*j;
            float term = Fk * cospif((float)(m*(2*lane + 1)) * (1.0f/(2*MC)));
            #pragma unroll
            for (int o = 16; o; o >>= 1) term += __shfl_xor_sync(0xffffffffu, term, o);
            if (lane == 0) {
                float cc = term * (2.0f/MC);
                if (m == 0) cc *= 0.5f;
                sCoef[m] = cc;
            }
        }
    }
    __syncthreads();

    // Clenshaw at 4 preloaded points/thread + row NDCG sum
    float ss[4] = {s4.x, s4.y, s4.z, s4.w};
    float numer = 0.f;
    #pragma unroll
    for (int i = 0; i < 4; i++) {
        float u = fminf(fmaxf(ss[i] * (1.0f/HH), -1.f), 1.f);
        float tu = u + u, y1 = 0.f, y2 = 0.f;
        #pragma unroll
        for (int m = MC - 1; m >= 1; m--) {
            float tmp = fmaf(tu, y1, sCoef[m]) - y2;
            y2 = y1; y1 = tmp;
        }
        float F = fmaf(u, y1, sCoef[0]) - y2;              // interpolated F(s)
        float gain = (float)((1 << vv[i]) - 1);
        numer += __fdividef(gain, __log2f(1.5f + F));      // pos = 0.5 + F
    }
    #pragma unroll
    for (int o = 16; o; o >>= 1) numer += __shfl_xor_sync(0xffffffffu, numer, o);
    if (lane == 0) sRed[w] = numer;
    __syncthreads();

    if (w == 0) {
        float x = (lane < 16) ? sRed[lane] : 0.f;
        #pragma unroll
        for (int o = 8; o; o >>= 1) x += __shfl_xor_sync(0xffffffffu, x, o);
        int d = 0;
        if (lane == 0) {
            g_rowSum[b] = x * inv;
            __threadfence();
            d = atomicAdd(&g_ctr, 1);
        }
        d = __shfl_sync(0xffffffffu, d, 0);
        if (d == BB - 1) {                        // last row finisher -> mean
            if (lane == 0) g_ctr = 0;             // self-reset
            __threadfence();
            float v = g_rowSum[lane];             // parallel read of 32 rows
            #pragma unroll
            for (int o = 16; o; o >>= 1) v += __shfl_xor_sync(0xffffffffu, v, o);
            if (lane == 0) out[0] = v * (1.0f/BB);
        }
    }
}

extern "C" void kernel_launch(void* const* d_in, const int* in_sizes, int n_in,
                              void* d_out, int out_size) {
    const float* yp = (const float*)d_in[0];
    const float* yt = (const float*)d_in[1];
    float* out = (float*)d_out;
    (void)in_sizes; (void)n_in; (void)out_size;

    dim3 g(PBLK + 1, BB);
    fused<<<g, 512>>>(yp, yt, out);
}